// round 5
// baseline (speedup 1.0000x reference)
#include <cuda_runtime.h>
#include <math.h>

#define BB 4
#define NN 2048
#define MM 2048

// ---- persistent scratch (device globals; no allocation allowed) ----
__device__ __align__(16) float g_d2[BB * NN * MM];   // 64 MB squared distances (L2-resident)
__device__ float g_remainL[BB * NN];
__device__ float g_remainR[BB * MM];
__device__ float g_ratioL[BB * NN];
__device__ float g_colA[BB * MM];   // colsum of w0*ratioL (for ratioR)
__device__ float g_colB[BB * MM];   // colsum of w (for remainR update)
__device__ float g_cost[BB];

// ---------------------------------------------------------------- init
__global__ void k_init() {
    int i = blockIdx.x * blockDim.x + threadIdx.x;
    if (i < BB * NN) g_remainL[i] = 1.0f;     // multiL = 1 (N == M)
    if (i < BB * MM) { g_remainR[i] = 1.0f; g_colA[i] = 0.0f; g_colB[i] = 0.0f; }
    if (i < BB) g_cost[i] = 0.0f;
}

// ------------------------------------------- d2 (literal fp32 rounding)
__global__ void k_d2(const float* __restrict__ tm, const float* __restrict__ sr) {
    __shared__ alignas(16) float sx[MM];
    __shared__ alignas(16) float sy[MM];
    __shared__ alignas(16) float sz[MM];
    int b = blockIdx.y;
    const float* sb = sr + (size_t)b * MM * 3;
    for (int i = threadIdx.x; i < MM; i += blockDim.x) {
        sx[i] = sb[3 * i]; sy[i] = sb[3 * i + 1]; sz[i] = sb[3 * i + 2];
    }
    __syncthreads();
    int warp = threadIdx.x >> 5, lane = threadIdx.x & 31;
    int n = blockIdx.x * 8 + warp;
    size_t row = (size_t)(b * NN + n);
    const float* tp = tm + row * 3;
    float tx = tp[0], ty = tp[1], tz = tp[2];
    float* drow = g_d2 + row * MM;
#pragma unroll 4
    for (int it = 0; it < 16; ++it) {
        int m = it * 128 + lane * 4;
        float4 X = *(const float4*)(sx + m);
        float4 Y = *(const float4*)(sy + m);
        float4 Z = *(const float4*)(sz + m);
        float4 o;
        { float dx = __fadd_rn(tx, -X.x), dy = __fadd_rn(ty, -Y.x), dz = __fadd_rn(tz, -Z.x);
          o.x = __fadd_rn(__fadd_rn(__fmul_rn(dx, dx), __fmul_rn(dy, dy)), __fmul_rn(dz, dz)); }
        { float dx = __fadd_rn(tx, -X.y), dy = __fadd_rn(ty, -Y.y), dz = __fadd_rn(tz, -Z.y);
          o.y = __fadd_rn(__fadd_rn(__fmul_rn(dx, dx), __fmul_rn(dy, dy)), __fmul_rn(dz, dz)); }
        { float dx = __fadd_rn(tx, -X.z), dy = __fadd_rn(ty, -Y.z), dz = __fadd_rn(tz, -Z.z);
          o.z = __fadd_rn(__fadd_rn(__fmul_rn(dx, dx), __fmul_rn(dy, dy)), __fmul_rn(dz, dz)); }
        { float dx = __fadd_rn(tx, -X.w), dy = __fadd_rn(ty, -Y.w), dz = __fadd_rn(tz, -Z.w);
          o.w = __fadd_rn(__fadd_rn(__fmul_rn(dx, dx), __fmul_rn(dy, dy)), __fmul_rn(dz, dz)); }
        *(float4*)(drow + m) = o;
    }
}

// --------------------------------------------------------------- kA
// Per level: w0 = expf(level*d2); suml per row -> ratioL; colA += w0*ratioL.
// 64 rows per block (8 warps x 8 rows), w0 recomputed for phase 2 (bit-identical).
__global__ void kA(float level) {
    __shared__ alignas(16) float s_rm[MM];    // remainR
    __shared__ float s_col[MM];               // block-local colsum
    int b = blockIdx.y;
    int row0 = blockIdx.x * 64;
    for (int i = threadIdx.x; i < MM; i += 256) {
        s_rm[i] = g_remainR[b * MM + i];
        s_col[i] = 0.0f;
    }
    __syncthreads();
    int warp = threadIdx.x >> 5, lane = threadIdx.x & 31;
#pragma unroll 1
    for (int r = 0; r < 8; ++r) {
        int n = row0 + warp * 8 + r;
        size_t row = (size_t)(b * NN + n);
        const float* drow = g_d2 + row * MM;
        // ---- phase 1: suml
        float suml = 0.0f;
#pragma unroll 2
        for (int it = 0; it < 16; ++it) {
            int m = it * 128 + lane * 4;
            float4 d4 = *(const float4*)(drow + m);
            float a0 = __fmul_rn(level, d4.x), a1 = __fmul_rn(level, d4.y);
            float a2 = __fmul_rn(level, d4.z), a3 = __fmul_rn(level, d4.w);
            float am = fmaxf(fmaxf(a0, a1), fmaxf(a2, a3));
            if (__any_sync(0xffffffffu, am > -105.0f)) {   // below: expf == +0, exact skip
                float w0 = expf(a0), w1 = expf(a1), w2 = expf(a2), w3 = expf(a3);
                float4 rm = *(const float4*)(s_rm + m);
                suml = fmaf(w0, rm.x, suml); suml = fmaf(w1, rm.y, suml);
                suml = fmaf(w2, rm.z, suml); suml = fmaf(w3, rm.w, suml);
            }
        }
#pragma unroll
        for (int o = 16; o; o >>= 1) suml += __shfl_xor_sync(0xffffffffu, suml, o);
        float ratioL = g_remainL[row] / (suml + 1e-9f);
        if (lane == 0) g_ratioL[row] = ratioL;
        // ---- phase 2: colA partials (w0 recomputed; d2 row is L1/L2-hot)
        if (__all_sync(0xffffffffu, ratioL == 0.0f)) continue;  // adds exact zeros
#pragma unroll 2
        for (int it = 0; it < 16; ++it) {
            int m = it * 128 + lane * 4;
            float4 d4 = *(const float4*)(drow + m);
            float a0 = __fmul_rn(level, d4.x), a1 = __fmul_rn(level, d4.y);
            float a2 = __fmul_rn(level, d4.z), a3 = __fmul_rn(level, d4.w);
            float am = fmaxf(fmaxf(a0, a1), fmaxf(a2, a3));
            if (__any_sync(0xffffffffu, am > -105.0f)) {
                atomicAdd(&s_col[m + 0], __fmul_rn(expf(a0), ratioL));
                atomicAdd(&s_col[m + 1], __fmul_rn(expf(a1), ratioL));
                atomicAdd(&s_col[m + 2], __fmul_rn(expf(a2), ratioL));
                atomicAdd(&s_col[m + 3], __fmul_rn(expf(a3), ratioL));
            }
        }
    }
    __syncthreads();
    for (int i = threadIdx.x; i < MM; i += 256) {
        float v = s_col[i];
        if (v != 0.0f) atomicAdd(&g_colA[b * MM + i], v);
    }
}

// --------------------------------------------------------------- kB
// ratioR = remainR/(colA+1e-9) inline; w = (w0*ratioL)*ratioR;
// remainL -= rowsum(w); colB += colsum(w); cost += w*sqrt(max(d2,1e-24)).
__global__ void kB(float level) {
    __shared__ alignas(16) float s_rr[MM];    // ratioR
    __shared__ float s_col[MM];
    __shared__ float s_cost[8];
    int b = blockIdx.y;
    int row0 = blockIdx.x * 64;
    for (int i = threadIdx.x; i < MM; i += 256) {
        s_rr[i] = g_remainR[b * MM + i] / (g_colA[b * MM + i] + 1e-9f);
        s_col[i] = 0.0f;
    }
    __syncthreads();
    int warp = threadIdx.x >> 5, lane = threadIdx.x & 31;
    float costw = 0.0f;
#pragma unroll 1
    for (int r = 0; r < 8; ++r) {
        int n = row0 + warp * 8 + r;
        size_t row = (size_t)(b * NN + n);
        const float* drow = g_d2 + row * MM;
        float rl = g_ratioL[row];
        float rowsum = 0.0f;
#pragma unroll 2
        for (int it = 0; it < 16; ++it) {
            int m = it * 128 + lane * 4;
            float4 d4 = *(const float4*)(drow + m);
            float a0 = __fmul_rn(level, d4.x), a1 = __fmul_rn(level, d4.y);
            float a2 = __fmul_rn(level, d4.z), a3 = __fmul_rn(level, d4.w);
            float am = fmaxf(fmaxf(a0, a1), fmaxf(a2, a3));
            if (!__any_sync(0xffffffffu, am > -105.0f)) continue;   // w == 0 exactly
            float4 rr = *(const float4*)(s_rr + m);
            float w0 = __fmul_rn(__fmul_rn(expf(a0), rl), rr.x);
            float w1 = __fmul_rn(__fmul_rn(expf(a1), rl), rr.y);
            float w2 = __fmul_rn(__fmul_rn(expf(a2), rl), rr.z);
            float w3 = __fmul_rn(__fmul_rn(expf(a3), rl), rr.w);
            rowsum = __fadd_rn(rowsum, __fadd_rn(__fadd_rn(w0, w1), __fadd_rn(w2, w3)));
            if (__any_sync(0xffffffffu,
                           (w0 != 0.0f) | (w1 != 0.0f) | (w2 != 0.0f) | (w3 != 0.0f))) {
                costw = fmaf(w0, sqrtf(fmaxf(d4.x, 1e-24f)), costw);
                costw = fmaf(w1, sqrtf(fmaxf(d4.y, 1e-24f)), costw);
                costw = fmaf(w2, sqrtf(fmaxf(d4.z, 1e-24f)), costw);
                costw = fmaf(w3, sqrtf(fmaxf(d4.w, 1e-24f)), costw);
                atomicAdd(&s_col[m + 0], w0);
                atomicAdd(&s_col[m + 1], w1);
                atomicAdd(&s_col[m + 2], w2);
                atomicAdd(&s_col[m + 3], w3);
            }
        }
#pragma unroll
        for (int o = 16; o; o >>= 1) rowsum += __shfl_xor_sync(0xffffffffu, rowsum, o);
        if (lane == 0)
            g_remainL[row] = fmaxf(__fadd_rn(g_remainL[row], -rowsum), 0.0f);
    }
    // cost reduction
#pragma unroll
    for (int o = 16; o; o >>= 1) costw += __shfl_xor_sync(0xffffffffu, costw, o);
    if (lane == 0) s_cost[warp] = costw;
    __syncthreads();
    if (threadIdx.x == 0) {
        float c = 0.0f;
#pragma unroll
        for (int w = 0; w < 8; ++w) c += s_cost[w];
        if (c != 0.0f) atomicAdd(&g_cost[b], c);
    }
    for (int i = threadIdx.x; i < MM; i += 256) {
        float v = s_col[i];
        if (v != 0.0f) atomicAdd(&g_colB[b * MM + i], v);
    }
}

// ---------------- remainR = max(remainR - colB, 0); reset col buffers
__global__ void kR() {
    int i = blockIdx.x * blockDim.x + threadIdx.x;
    if (i >= BB * MM) return;
    g_remainR[i] = fmaxf(__fadd_rn(g_remainR[i], -g_colB[i]), 0.0f);
    g_colA[i] = 0.0f;
    g_colB[i] = 0.0f;
}

__global__ void k_out(float* out) {
    out[0] = (g_cost[0] + g_cost[1] + g_cost[2] + g_cost[3]) * (1.0f / (BB * NN));
}

// ---------------------------------------------------------------- host
extern "C" void kernel_launch(void* const* d_in, const int* in_sizes, int n_in,
                              void* d_out, int out_size) {
    const float* tm = (const float*)d_in[0];
    const float* sr = (const float*)d_in[1];

    // levels: -4^7 .. -4^-1, then 0
    float kl[10];
    double lv = -16384.0;
    for (int j = 0; j < 8; ++j) { kl[j] = (float)lv; lv *= 0.25; }
    kl[8] = -0.25f;
    kl[9] = 0.0f;

    dim3 gM(32, BB);    // 64 rows per block
    k_init<<<16, 512>>>();
    k_d2<<<dim3(256, BB), 256>>>(tm, sr);
    for (int j = 0; j < 10; ++j) {
        kA<<<gM, 256>>>(kl[j]);
        kB<<<gM, 256>>>(kl[j]);
        kR<<<16, 512>>>();
    }
    k_out<<<1, 1>>>((float*)d_out);
}

// round 6
// speedup vs baseline: 2.5287x; 2.5287x over previous
#include <cuda_runtime.h>
#include <math.h>

#define BB 4
#define NN 2048
#define MM 2048

// ---- persistent scratch (device globals; no allocation allowed) ----
__device__ __align__(16) float g_d2[BB * NN * MM];   // 64 MB squared distances (L2-resident)
__device__ float g_remainL[BB * NN];
__device__ float g_remainR[BB * MM];
__device__ float g_ratioL[BB * NN];
__device__ float g_colA[BB * MM];   // colsum of w0*ratioL (for ratioR)
__device__ float g_colB[BB * MM];   // colsum of w (for remainR update)
__device__ float g_cost[BB];

// ---------------------------------------------------------------- init
__global__ void k_init() {
    int i = blockIdx.x * blockDim.x + threadIdx.x;
    if (i < BB * NN) g_remainL[i] = 1.0f;     // multiL = 1 (N == M)
    if (i < BB * MM) { g_remainR[i] = 1.0f; g_colA[i] = 0.0f; g_colB[i] = 0.0f; }
    if (i < BB) g_cost[i] = 0.0f;
}

// ------------------------------------------- d2 (literal fp32 rounding)
__global__ void k_d2(const float* __restrict__ tm, const float* __restrict__ sr) {
    __shared__ alignas(16) float sx[MM];
    __shared__ alignas(16) float sy[MM];
    __shared__ alignas(16) float sz[MM];
    int b = blockIdx.y;
    const float* sb = sr + (size_t)b * MM * 3;
    for (int i = threadIdx.x; i < MM; i += blockDim.x) {
        sx[i] = sb[3 * i]; sy[i] = sb[3 * i + 1]; sz[i] = sb[3 * i + 2];
    }
    __syncthreads();
    int warp = threadIdx.x >> 5, lane = threadIdx.x & 31;
    int n = blockIdx.x * 8 + warp;
    size_t row = (size_t)(b * NN + n);
    const float* tp = tm + row * 3;
    float tx = tp[0], ty = tp[1], tz = tp[2];
    float* drow = g_d2 + row * MM;
#pragma unroll 4
    for (int it = 0; it < 16; ++it) {
        int m = it * 128 + lane * 4;
        float4 X = *(const float4*)(sx + m);
        float4 Y = *(const float4*)(sy + m);
        float4 Z = *(const float4*)(sz + m);
        float4 o;
        { float dx = __fadd_rn(tx, -X.x), dy = __fadd_rn(ty, -Y.x), dz = __fadd_rn(tz, -Z.x);
          o.x = __fadd_rn(__fadd_rn(__fmul_rn(dx, dx), __fmul_rn(dy, dy)), __fmul_rn(dz, dz)); }
        { float dx = __fadd_rn(tx, -X.y), dy = __fadd_rn(ty, -Y.y), dz = __fadd_rn(tz, -Z.y);
          o.y = __fadd_rn(__fadd_rn(__fmul_rn(dx, dx), __fmul_rn(dy, dy)), __fmul_rn(dz, dz)); }
        { float dx = __fadd_rn(tx, -X.z), dy = __fadd_rn(ty, -Y.z), dz = __fadd_rn(tz, -Z.z);
          o.z = __fadd_rn(__fadd_rn(__fmul_rn(dx, dx), __fmul_rn(dy, dy)), __fmul_rn(dz, dz)); }
        { float dx = __fadd_rn(tx, -X.w), dy = __fadd_rn(ty, -Y.w), dz = __fadd_rn(tz, -Z.w);
          o.w = __fadd_rn(__fadd_rn(__fmul_rn(dx, dx), __fmul_rn(dy, dy)), __fmul_rn(dz, dz)); }
        *(float4*)(drow + m) = o;
    }
}

// --------------------------------------------------------------- kA
// 16 rows/block. Phase 1 (row-major): suml -> ratioL.
// Phase 2 (column-ownership): colA[c] += sum_rows w0*ratioL, registers only.
__global__ void kA(float level) {
    __shared__ alignas(16) float s_rm[MM];    // remainR
    __shared__ float s_rl[16];                // ratioL for this block's rows
    int b = blockIdx.y;
    int row0 = blockIdx.x * 16;
    for (int i = threadIdx.x; i < MM; i += 256) s_rm[i] = g_remainR[b * MM + i];
    __syncthreads();
    int warp = threadIdx.x >> 5, lane = threadIdx.x & 31;
    // ---- phase 1: 8 warps x 2 rows
#pragma unroll 1
    for (int r2 = 0; r2 < 2; ++r2) {
        int rloc = warp * 2 + r2;
        size_t row = (size_t)(b * NN + row0 + rloc);
        const float* drow = g_d2 + row * MM;
        float suml = 0.0f;
#pragma unroll 2
        for (int it = 0; it < 16; ++it) {
            int m = it * 128 + lane * 4;
            float4 d4 = *(const float4*)(drow + m);
            float a0 = __fmul_rn(level, d4.x), a1 = __fmul_rn(level, d4.y);
            float a2 = __fmul_rn(level, d4.z), a3 = __fmul_rn(level, d4.w);
            float am = fmaxf(fmaxf(a0, a1), fmaxf(a2, a3));
            if (__any_sync(0xffffffffu, am > -105.0f)) {   // below: expf == +0, exact skip
                float4 rm = *(const float4*)(s_rm + m);
                suml = fmaf(expf(a0), rm.x, suml); suml = fmaf(expf(a1), rm.y, suml);
                suml = fmaf(expf(a2), rm.z, suml); suml = fmaf(expf(a3), rm.w, suml);
            }
        }
#pragma unroll
        for (int o = 16; o; o >>= 1) suml += __shfl_xor_sync(0xffffffffu, suml, o);
        if (lane == 0) {
            float rl = g_remainL[row] / (suml + 1e-9f);
            s_rl[rloc] = rl;
            g_ratioL[row] = rl;
        }
    }
    __syncthreads();
    // ---- phase 2: thread owns cols c, c+256, ..., c+1792
    int c = threadIdx.x;
    float acc[8] = {0, 0, 0, 0, 0, 0, 0, 0};
#pragma unroll 1
    for (int r = 0; r < 16; ++r) {
        const float* drow = g_d2 + ((size_t)(b * NN + row0 + r)) * MM;
        float rl = s_rl[r];
#pragma unroll
        for (int k = 0; k < 8; ++k) {
            float a = __fmul_rn(level, drow[c + k * 256]);
            if (__any_sync(0xffffffffu, a > -105.0f))
                acc[k] = fmaf(expf(a), rl, acc[k]);
        }
    }
#pragma unroll
    for (int k = 0; k < 8; ++k)
        if (acc[k] != 0.0f) atomicAdd(&g_colA[b * MM + c + k * 256], acc[k]);
}

// --------------------------------------------------------------- kB
// ratioR inline; w = (w0*ratioL)*ratioR; per-thread register colsums;
// rowsum via warp shuffle + per-warp smem atomic; cost in registers.
__global__ void kB(float level) {
    __shared__ alignas(16) float s_rr[MM];    // ratioR
    __shared__ float s_rl[16];
    __shared__ float s_rowsum[16];
    __shared__ float s_cost[8];
    int b = blockIdx.y;
    int row0 = blockIdx.x * 16;
    for (int i = threadIdx.x; i < MM; i += 256)
        s_rr[i] = g_remainR[b * MM + i] / (g_colA[b * MM + i] + 1e-9f);
    if (threadIdx.x < 16) {
        s_rl[threadIdx.x] = g_ratioL[b * NN + row0 + threadIdx.x];
        s_rowsum[threadIdx.x] = 0.0f;
    }
    __syncthreads();
    int warp = threadIdx.x >> 5, lane = threadIdx.x & 31;
    int c = threadIdx.x;
    float rr[8], colacc[8];
#pragma unroll
    for (int k = 0; k < 8; ++k) { rr[k] = s_rr[c + k * 256]; colacc[k] = 0.0f; }
    float costw = 0.0f;
#pragma unroll 1
    for (int r = 0; r < 16; ++r) {
        float rl = s_rl[r];
        if (rl == 0.0f) continue;              // w row == 0 exactly
        const float* drow = g_d2 + ((size_t)(b * NN + row0 + r)) * MM;
        float rowpart = 0.0f;
#pragma unroll
        for (int k = 0; k < 8; ++k) {
            float dv = drow[c + k * 256];
            float a = __fmul_rn(level, dv);
            if (__any_sync(0xffffffffu, a > -105.0f)) {
                float w = __fmul_rn(__fmul_rn(expf(a), rl), rr[k]);
                colacc[k] = __fadd_rn(colacc[k], w);
                rowpart = __fadd_rn(rowpart, w);
                costw = fmaf(w, sqrtf(fmaxf(dv, 1e-24f)), costw);
            }
        }
#pragma unroll
        for (int o = 16; o; o >>= 1) rowpart += __shfl_xor_sync(0xffffffffu, rowpart, o);
        if (lane == 0 && rowpart != 0.0f) atomicAdd(&s_rowsum[r], rowpart);
    }
    // cost reduction
#pragma unroll
    for (int o = 16; o; o >>= 1) costw += __shfl_xor_sync(0xffffffffu, costw, o);
    if (lane == 0) s_cost[warp] = costw;
    __syncthreads();
    if (threadIdx.x < 16) {
        size_t row = (size_t)(b * NN + row0 + threadIdx.x);
        g_remainL[row] = fmaxf(__fadd_rn(g_remainL[row], -s_rowsum[threadIdx.x]), 0.0f);
    }
    if (threadIdx.x == 0) {
        float cc = 0.0f;
#pragma unroll
        for (int w = 0; w < 8; ++w) cc += s_cost[w];
        if (cc != 0.0f) atomicAdd(&g_cost[b], cc);
    }
#pragma unroll
    for (int k = 0; k < 8; ++k)
        if (colacc[k] != 0.0f) atomicAdd(&g_colB[b * MM + c + k * 256], colacc[k]);
}

// ---------------- remainR = max(remainR - colB, 0); reset col buffers
__global__ void kR() {
    int i = blockIdx.x * blockDim.x + threadIdx.x;
    if (i >= BB * MM) return;
    g_remainR[i] = fmaxf(__fadd_rn(g_remainR[i], -g_colB[i]), 0.0f);
    g_colA[i] = 0.0f;
    g_colB[i] = 0.0f;
}

__global__ void k_out(float* out) {
    out[0] = (g_cost[0] + g_cost[1] + g_cost[2] + g_cost[3]) * (1.0f / (BB * NN));
}

// ---------------------------------------------------------------- host
extern "C" void kernel_launch(void* const* d_in, const int* in_sizes, int n_in,
                              void* d_out, int out_size) {
    const float* tm = (const float*)d_in[0];
    const float* sr = (const float*)d_in[1];

    // levels: -4^7 .. -4^-1, then 0
    float kl[10];
    double lv = -16384.0;
    for (int j = 0; j < 8; ++j) { kl[j] = (float)lv; lv *= 0.25; }
    kl[8] = -0.25f;
    kl[9] = 0.0f;

    dim3 gM(128, BB);    // 16 rows per block -> 512 blocks
    k_init<<<16, 512>>>();
    k_d2<<<dim3(256, BB), 256>>>(tm, sr);
    for (int j = 0; j < 10; ++j) {
        kA<<<gM, 256>>>(kl[j]);
        kB<<<gM, 256>>>(kl[j]);
        kR<<<16, 512>>>();
    }
    k_out<<<1, 1>>>((float*)d_out);
}

// round 7
// speedup vs baseline: 2.6648x; 1.0538x over previous
#include <cuda_runtime.h>
#include <math.h>

#define BB 4
#define NN 2048
#define MM 2048

// ---- persistent scratch (device globals; no allocation allowed) ----
__device__ __align__(16) float g_d2[BB * NN * MM];   // 64 MB squared distances (L2-resident)
__device__ float g_cmin[BB * NN * 16];               // per-row 128-col chunk minima
__device__ float g_remainL[BB * NN];
__device__ float g_remainR[BB * MM];
__device__ float g_ratioL[BB * NN];
__device__ float g_colA[BB * MM];   // colsum of w0*ratioL (for ratioR)
__device__ float g_colB[BB * MM];   // colsum of w (for remainR update)
__device__ float g_cost[BB];

// ---------------------------------------------------------------- init
__global__ void k_init() {
    int i = blockIdx.x * blockDim.x + threadIdx.x;
    if (i < BB * NN) g_remainL[i] = 1.0f;     // multiL = 1 (N == M)
    if (i < BB * MM) { g_remainR[i] = 1.0f; g_colA[i] = 0.0f; g_colB[i] = 0.0f; }
    if (i < BB) g_cost[i] = 0.0f;
}

// ---------------------- d2 (literal fp32 rounding) + chunk minima
__global__ void k_d2(const float* __restrict__ tm, const float* __restrict__ sr) {
    __shared__ alignas(16) float sx[MM];
    __shared__ alignas(16) float sy[MM];
    __shared__ alignas(16) float sz[MM];
    int b = blockIdx.y;
    const float* sb = sr + (size_t)b * MM * 3;
    for (int i = threadIdx.x; i < MM; i += blockDim.x) {
        sx[i] = sb[3 * i]; sy[i] = sb[3 * i + 1]; sz[i] = sb[3 * i + 2];
    }
    __syncthreads();
    int warp = threadIdx.x >> 5, lane = threadIdx.x & 31;
    int n = blockIdx.x * 8 + warp;
    size_t row = (size_t)(b * NN + n);
    const float* tp = tm + row * 3;
    float tx = tp[0], ty = tp[1], tz = tp[2];
    float* drow = g_d2 + row * MM;
#pragma unroll 2
    for (int it = 0; it < 16; ++it) {
        int m = it * 128 + lane * 4;
        float4 X = *(const float4*)(sx + m);
        float4 Y = *(const float4*)(sy + m);
        float4 Z = *(const float4*)(sz + m);
        float4 o;
        { float dx = __fadd_rn(tx, -X.x), dy = __fadd_rn(ty, -Y.x), dz = __fadd_rn(tz, -Z.x);
          o.x = __fadd_rn(__fadd_rn(__fmul_rn(dx, dx), __fmul_rn(dy, dy)), __fmul_rn(dz, dz)); }
        { float dx = __fadd_rn(tx, -X.y), dy = __fadd_rn(ty, -Y.y), dz = __fadd_rn(tz, -Z.y);
          o.y = __fadd_rn(__fadd_rn(__fmul_rn(dx, dx), __fmul_rn(dy, dy)), __fmul_rn(dz, dz)); }
        { float dx = __fadd_rn(tx, -X.z), dy = __fadd_rn(ty, -Y.z), dz = __fadd_rn(tz, -Z.z);
          o.z = __fadd_rn(__fadd_rn(__fmul_rn(dx, dx), __fmul_rn(dy, dy)), __fmul_rn(dz, dz)); }
        { float dx = __fadd_rn(tx, -X.w), dy = __fadd_rn(ty, -Y.w), dz = __fadd_rn(tz, -Z.w);
          o.w = __fadd_rn(__fadd_rn(__fmul_rn(dx, dx), __fmul_rn(dy, dy)), __fmul_rn(dz, dz)); }
        *(float4*)(drow + m) = o;
        float mn = fminf(fminf(o.x, o.y), fminf(o.z, o.w));
#pragma unroll
        for (int s = 16; s; s >>= 1) mn = fminf(mn, __shfl_xor_sync(0xffffffffu, mn, s));
        if (lane == 0) g_cmin[row * 16 + it] = mn;
    }
}

// --------------------------------------------------------------- kA
// 8 rows/block (grid 1024). Phase 1: suml -> ratioL (1 row/warp).
// Phase 2 (column-ownership, float4): colA[c] += sum_rows w0*ratioL.
// Chunk skip: rn(level*cmin) <= -105  <=>  all 128 exps flush to +0 (exact).
__global__ void kA(float level) {
    __shared__ alignas(16) float s_rm[MM];    // remainR
    __shared__ float s_rl[8];
    int b = blockIdx.y;
    int row0 = blockIdx.x * 8;
    for (int i = threadIdx.x; i < MM; i += 256) s_rm[i] = g_remainR[b * MM + i];
    __syncthreads();
    int warp = threadIdx.x >> 5, lane = threadIdx.x & 31;
    // ---- phase 1: one row per warp
    {
        size_t row = (size_t)(b * NN + row0 + warp);
        const float* drow = g_d2 + row * MM;
        const float* cmin = g_cmin + row * 16;
        float suml = 0.0f;
#pragma unroll 2
        for (int it = 0; it < 16; ++it) {
            if (__fmul_rn(level, cmin[it]) > -105.0f) {
                int m = it * 128 + lane * 4;
                float4 d4 = *(const float4*)(drow + m);
                float4 rm = *(const float4*)(s_rm + m);
                suml = fmaf(expf(__fmul_rn(level, d4.x)), rm.x, suml);
                suml = fmaf(expf(__fmul_rn(level, d4.y)), rm.y, suml);
                suml = fmaf(expf(__fmul_rn(level, d4.z)), rm.z, suml);
                suml = fmaf(expf(__fmul_rn(level, d4.w)), rm.w, suml);
            }
        }
#pragma unroll
        for (int o = 16; o; o >>= 1) suml += __shfl_xor_sync(0xffffffffu, suml, o);
        if (lane == 0) {
            float rl = g_remainL[row] / (suml + 1e-9f);
            s_rl[warp] = rl;
            g_ratioL[row] = rl;
        }
    }
    __syncthreads();
    // ---- phase 2: thread owns cols 4*tid + 1024*k (k = 0,1)
    int c4 = threadIdx.x * 4;
    float4 acc0 = make_float4(0, 0, 0, 0), acc1 = make_float4(0, 0, 0, 0);
    int ch0 = warp, ch1 = warp + 8;   // chunk index for k=0,1 (warp-uniform)
#pragma unroll 1
    for (int r = 0; r < 8; ++r) {
        size_t row = (size_t)(b * NN + row0 + r);
        const float* drow = g_d2 + row * MM;
        const float* cmin = g_cmin + row * 16;
        float rl = s_rl[r];
        if (__fmul_rn(level, cmin[ch0]) > -105.0f) {
            float4 d4 = *(const float4*)(drow + c4);
            acc0.x = fmaf(expf(__fmul_rn(level, d4.x)), rl, acc0.x);
            acc0.y = fmaf(expf(__fmul_rn(level, d4.y)), rl, acc0.y);
            acc0.z = fmaf(expf(__fmul_rn(level, d4.z)), rl, acc0.z);
            acc0.w = fmaf(expf(__fmul_rn(level, d4.w)), rl, acc0.w);
        }
        if (__fmul_rn(level, cmin[ch1]) > -105.0f) {
            float4 d4 = *(const float4*)(drow + c4 + 1024);
            acc1.x = fmaf(expf(__fmul_rn(level, d4.x)), rl, acc1.x);
            acc1.y = fmaf(expf(__fmul_rn(level, d4.y)), rl, acc1.y);
            acc1.z = fmaf(expf(__fmul_rn(level, d4.z)), rl, acc1.z);
            acc1.w = fmaf(expf(__fmul_rn(level, d4.w)), rl, acc1.w);
        }
    }
    float* colA = g_colA + b * MM;
    if (acc0.x != 0.0f) atomicAdd(&colA[c4 + 0], acc0.x);
    if (acc0.y != 0.0f) atomicAdd(&colA[c4 + 1], acc0.y);
    if (acc0.z != 0.0f) atomicAdd(&colA[c4 + 2], acc0.z);
    if (acc0.w != 0.0f) atomicAdd(&colA[c4 + 3], acc0.w);
    if (acc1.x != 0.0f) atomicAdd(&colA[c4 + 1024], acc1.x);
    if (acc1.y != 0.0f) atomicAdd(&colA[c4 + 1025], acc1.y);
    if (acc1.z != 0.0f) atomicAdd(&colA[c4 + 1026], acc1.z);
    if (acc1.w != 0.0f) atomicAdd(&colA[c4 + 1027], acc1.w);
}

// --------------------------------------------------------------- kB
// ratioR inline; w = (w0*ratioL)*ratioR; register colsums (float4);
// rowsum via warp shuffle + per-warp smem atomic; cost in registers.
__global__ void kB(float level) {
    __shared__ alignas(16) float s_rr[MM];    // ratioR
    __shared__ float s_rl[8];
    __shared__ float s_rowsum[8];
    __shared__ float s_cost[8];
    int b = blockIdx.y;
    int row0 = blockIdx.x * 8;
    for (int i = threadIdx.x; i < MM; i += 256)
        s_rr[i] = g_remainR[b * MM + i] / (g_colA[b * MM + i] + 1e-9f);
    if (threadIdx.x < 8) {
        s_rl[threadIdx.x] = g_ratioL[b * NN + row0 + threadIdx.x];
        s_rowsum[threadIdx.x] = 0.0f;
    }
    __syncthreads();
    int warp = threadIdx.x >> 5, lane = threadIdx.x & 31;
    int c4 = threadIdx.x * 4;
    int ch0 = warp, ch1 = warp + 8;
    float4 rr0 = *(const float4*)(s_rr + c4);
    float4 rr1 = *(const float4*)(s_rr + c4 + 1024);
    float4 col0 = make_float4(0, 0, 0, 0), col1 = make_float4(0, 0, 0, 0);
    float costw = 0.0f;
#pragma unroll 1
    for (int r = 0; r < 8; ++r) {
        float rl = s_rl[r];
        if (rl == 0.0f) continue;             // w row == 0 exactly
        size_t row = (size_t)(b * NN + row0 + r);
        const float* drow = g_d2 + row * MM;
        const float* cmin = g_cmin + row * 16;
        float rowpart = 0.0f;
        if (__fmul_rn(level, cmin[ch0]) > -105.0f) {
            float4 d4 = *(const float4*)(drow + c4);
            float w0 = __fmul_rn(__fmul_rn(expf(__fmul_rn(level, d4.x)), rl), rr0.x);
            float w1 = __fmul_rn(__fmul_rn(expf(__fmul_rn(level, d4.y)), rl), rr0.y);
            float w2 = __fmul_rn(__fmul_rn(expf(__fmul_rn(level, d4.z)), rl), rr0.z);
            float w3 = __fmul_rn(__fmul_rn(expf(__fmul_rn(level, d4.w)), rl), rr0.w);
            col0.x = __fadd_rn(col0.x, w0); col0.y = __fadd_rn(col0.y, w1);
            col0.z = __fadd_rn(col0.z, w2); col0.w = __fadd_rn(col0.w, w3);
            rowpart = __fadd_rn(rowpart, __fadd_rn(__fadd_rn(w0, w1), __fadd_rn(w2, w3)));
            costw = fmaf(w0, sqrtf(fmaxf(d4.x, 1e-24f)), costw);
            costw = fmaf(w1, sqrtf(fmaxf(d4.y, 1e-24f)), costw);
            costw = fmaf(w2, sqrtf(fmaxf(d4.z, 1e-24f)), costw);
            costw = fmaf(w3, sqrtf(fmaxf(d4.w, 1e-24f)), costw);
        }
        if (__fmul_rn(level, cmin[ch1]) > -105.0f) {
            float4 d4 = *(const float4*)(drow + c4 + 1024);
            float w0 = __fmul_rn(__fmul_rn(expf(__fmul_rn(level, d4.x)), rl), rr1.x);
            float w1 = __fmul_rn(__fmul_rn(expf(__fmul_rn(level, d4.y)), rl), rr1.y);
            float w2 = __fmul_rn(__fmul_rn(expf(__fmul_rn(level, d4.z)), rl), rr1.z);
            float w3 = __fmul_rn(__fmul_rn(expf(__fmul_rn(level, d4.w)), rl), rr1.w);
            col1.x = __fadd_rn(col1.x, w0); col1.y = __fadd_rn(col1.y, w1);
            col1.z = __fadd_rn(col1.z, w2); col1.w = __fadd_rn(col1.w, w3);
            rowpart = __fadd_rn(rowpart, __fadd_rn(__fadd_rn(w0, w1), __fadd_rn(w2, w3)));
            costw = fmaf(w0, sqrtf(fmaxf(d4.x, 1e-24f)), costw);
            costw = fmaf(w1, sqrtf(fmaxf(d4.y, 1e-24f)), costw);
            costw = fmaf(w2, sqrtf(fmaxf(d4.z, 1e-24f)), costw);
            costw = fmaf(w3, sqrtf(fmaxf(d4.w, 1e-24f)), costw);
        }
#pragma unroll
        for (int o = 16; o; o >>= 1) rowpart += __shfl_xor_sync(0xffffffffu, rowpart, o);
        if (lane == 0 && rowpart != 0.0f) atomicAdd(&s_rowsum[r], rowpart);
    }
    // cost reduction
#pragma unroll
    for (int o = 16; o; o >>= 1) costw += __shfl_xor_sync(0xffffffffu, costw, o);
    if (lane == 0) s_cost[warp] = costw;
    __syncthreads();
    if (threadIdx.x < 8) {
        size_t row = (size_t)(b * NN + row0 + threadIdx.x);
        g_remainL[row] = fmaxf(__fadd_rn(g_remainL[row], -s_rowsum[threadIdx.x]), 0.0f);
    }
    if (threadIdx.x == 0) {
        float cc = 0.0f;
#pragma unroll
        for (int w = 0; w < 8; ++w) cc += s_cost[w];
        if (cc != 0.0f) atomicAdd(&g_cost[b], cc);
    }
    float* colB = g_colB + b * MM;
    if (col0.x != 0.0f) atomicAdd(&colB[c4 + 0], col0.x);
    if (col0.y != 0.0f) atomicAdd(&colB[c4 + 1], col0.y);
    if (col0.z != 0.0f) atomicAdd(&colB[c4 + 2], col0.z);
    if (col0.w != 0.0f) atomicAdd(&colB[c4 + 3], col0.w);
    if (col1.x != 0.0f) atomicAdd(&colB[c4 + 1024], col1.x);
    if (col1.y != 0.0f) atomicAdd(&colB[c4 + 1025], col1.y);
    if (col1.z != 0.0f) atomicAdd(&colB[c4 + 1026], col1.z);
    if (col1.w != 0.0f) atomicAdd(&colB[c4 + 1027], col1.w);
}

// ---------------- remainR = max(remainR - colB, 0); reset col buffers
__global__ void kR() {
    int i = blockIdx.x * blockDim.x + threadIdx.x;
    if (i >= BB * MM) return;
    g_remainR[i] = fmaxf(__fadd_rn(g_remainR[i], -g_colB[i]), 0.0f);
    g_colA[i] = 0.0f;
    g_colB[i] = 0.0f;
}

__global__ void k_out(float* out) {
    out[0] = (g_cost[0] + g_cost[1] + g_cost[2] + g_cost[3]) * (1.0f / (BB * NN));
}

// ---------------------------------------------------------------- host
extern "C" void kernel_launch(void* const* d_in, const int* in_sizes, int n_in,
                              void* d_out, int out_size) {
    const float* tm = (const float*)d_in[0];
    const float* sr = (const float*)d_in[1];

    // levels: -4^7 .. -4^-1, then 0
    float kl[10];
    double lv = -16384.0;
    for (int j = 0; j < 8; ++j) { kl[j] = (float)lv; lv *= 0.25; }
    kl[8] = -0.25f;
    kl[9] = 0.0f;

    dim3 gM(256, BB);    // 8 rows per block -> 1024 blocks
    k_init<<<16, 512>>>();
    k_d2<<<dim3(256, BB), 256>>>(tm, sr);
    for (int j = 0; j < 10; ++j) {
        kA<<<gM, 256>>>(kl[j]);
        kB<<<gM, 256>>>(kl[j]);
        kR<<<16, 512>>>();
    }
    k_out<<<1, 1>>>((float*)d_out);
}

// round 8
// speedup vs baseline: 3.1769x; 1.1922x over previous
#include <cuda_runtime.h>
#include <math.h>

#define BB 4
#define NN 2048
#define MM 2048

// ---- persistent scratch (device globals; no allocation allowed) ----
__device__ __align__(16) float g_d2[BB * NN * MM];   // 64 MB squared distances (L2-resident)
__device__ float g_cmin[BB * NN * 16];               // per-row 128-col chunk minima
__device__ float g_remainL[BB * NN];
__device__ float g_remainR[BB * MM];
__device__ float g_ratioL[BB * NN];
__device__ float g_colA[BB * MM];   // colsum of w0*ratioL (for ratioR)
__device__ float g_colB[BB * MM];   // colsum of w (for remainR update)
__device__ float g_cost[BB];

__device__ __forceinline__ float ex2a(float x) {
    float y; asm("ex2.approx.f32 %0, %1;" : "=f"(y) : "f"(x)); return y;
}
__device__ __forceinline__ float sqrta(float x) {
    float y; asm("sqrt.approx.f32 %0, %1;" : "=f"(y) : "f"(x)); return y;
}

// ---------------------------------------------------------------- init
__global__ void k_init() {
    int i = blockIdx.x * blockDim.x + threadIdx.x;
    if (i < BB * NN) g_remainL[i] = 1.0f;     // multiL = 1 (N == M)
    if (i < BB * MM) { g_remainR[i] = 1.0f; g_colA[i] = 0.0f; g_colB[i] = 0.0f; }
    if (i < BB) g_cost[i] = 0.0f;
}

// ---------------------- d2 (literal fp32 rounding) + chunk minima
__global__ void k_d2(const float* __restrict__ tm, const float* __restrict__ sr) {
    __shared__ alignas(16) float sx[MM];
    __shared__ alignas(16) float sy[MM];
    __shared__ alignas(16) float sz[MM];
    int b = blockIdx.y;
    const float* sb = sr + (size_t)b * MM * 3;
    for (int i = threadIdx.x; i < MM; i += blockDim.x) {
        sx[i] = sb[3 * i]; sy[i] = sb[3 * i + 1]; sz[i] = sb[3 * i + 2];
    }
    __syncthreads();
    int warp = threadIdx.x >> 5, lane = threadIdx.x & 31;
    int n = blockIdx.x * 8 + warp;
    size_t row = (size_t)(b * NN + n);
    const float* tp = tm + row * 3;
    float tx = tp[0], ty = tp[1], tz = tp[2];
    float* drow = g_d2 + row * MM;
#pragma unroll 2
    for (int it = 0; it < 16; ++it) {
        int m = it * 128 + lane * 4;
        float4 X = *(const float4*)(sx + m);
        float4 Y = *(const float4*)(sy + m);
        float4 Z = *(const float4*)(sz + m);
        float4 o;
        { float dx = __fadd_rn(tx, -X.x), dy = __fadd_rn(ty, -Y.x), dz = __fadd_rn(tz, -Z.x);
          o.x = __fadd_rn(__fadd_rn(__fmul_rn(dx, dx), __fmul_rn(dy, dy)), __fmul_rn(dz, dz)); }
        { float dx = __fadd_rn(tx, -X.y), dy = __fadd_rn(ty, -Y.y), dz = __fadd_rn(tz, -Z.y);
          o.y = __fadd_rn(__fadd_rn(__fmul_rn(dx, dx), __fmul_rn(dy, dy)), __fmul_rn(dz, dz)); }
        { float dx = __fadd_rn(tx, -X.z), dy = __fadd_rn(ty, -Y.z), dz = __fadd_rn(tz, -Z.z);
          o.z = __fadd_rn(__fadd_rn(__fmul_rn(dx, dx), __fmul_rn(dy, dy)), __fmul_rn(dz, dz)); }
        { float dx = __fadd_rn(tx, -X.w), dy = __fadd_rn(ty, -Y.w), dz = __fadd_rn(tz, -Z.w);
          o.w = __fadd_rn(__fadd_rn(__fmul_rn(dx, dx), __fmul_rn(dy, dy)), __fmul_rn(dz, dz)); }
        *(float4*)(drow + m) = o;
        float mn = fminf(fminf(o.x, o.y), fminf(o.z, o.w));
#pragma unroll
        for (int s = 16; s; s >>= 1) mn = fminf(mn, __shfl_xor_sync(0xffffffffu, mn, s));
        if (lane == 0) g_cmin[row * 16 + it] = mn;
    }
}

// --------------------------------------------------------------- kA
// 8 rows/block (grid 1024). Phase 1: suml -> ratioL (1 row/warp).
// Phase 2 (column-ownership, float4): colA[c] += sum_rows w0*ratioL.
// Chunk skip: rn(kl2*cmin) <= -126 (log2 units) => all 128 ex2 flush to 0.
__global__ void kA(float kl2) {   // kl2 = level * log2(e)
    __shared__ alignas(16) float s_rm[MM];    // remainR
    __shared__ float s_rl[8];
    __shared__ float s_cm[8 * 16];            // cmin cache for the block's rows
    int b = blockIdx.y;
    int row0 = blockIdx.x * 8;
    for (int i = threadIdx.x; i < MM; i += 256) s_rm[i] = g_remainR[b * MM + i];
    if (threadIdx.x < 128)
        s_cm[threadIdx.x] = g_cmin[(size_t)(b * NN + row0) * 16 + threadIdx.x];
    __syncthreads();
    int warp = threadIdx.x >> 5, lane = threadIdx.x & 31;
    // ---- phase 1: one row per warp
    {
        size_t row = (size_t)(b * NN + row0 + warp);
        const float* drow = g_d2 + row * MM;
        float suml = 0.0f;
#pragma unroll 2
        for (int it = 0; it < 16; ++it) {
            if (__fmul_rn(kl2, s_cm[warp * 16 + it]) > -126.0f) {
                int m = it * 128 + lane * 4;
                float4 d4 = *(const float4*)(drow + m);
                float4 rm = *(const float4*)(s_rm + m);
                suml = fmaf(ex2a(__fmul_rn(kl2, d4.x)), rm.x, suml);
                suml = fmaf(ex2a(__fmul_rn(kl2, d4.y)), rm.y, suml);
                suml = fmaf(ex2a(__fmul_rn(kl2, d4.z)), rm.z, suml);
                suml = fmaf(ex2a(__fmul_rn(kl2, d4.w)), rm.w, suml);
            }
        }
#pragma unroll
        for (int o = 16; o; o >>= 1) suml += __shfl_xor_sync(0xffffffffu, suml, o);
        if (lane == 0) {
            float rl = g_remainL[row] / (suml + 1e-9f);
            s_rl[warp] = rl;
            g_ratioL[row] = rl;
        }
    }
    __syncthreads();
    // ---- phase 2: thread owns cols 4*tid + 1024*k (k = 0,1)
    int c4 = threadIdx.x * 4;
    float4 acc0 = make_float4(0, 0, 0, 0), acc1 = make_float4(0, 0, 0, 0);
    int ch0 = warp, ch1 = warp + 8;   // warp-uniform chunk indices
#pragma unroll 2
    for (int r = 0; r < 8; ++r) {
        const float* drow = g_d2 + ((size_t)(b * NN + row0 + r)) * MM;
        float rl = s_rl[r];
        bool a0 = __fmul_rn(kl2, s_cm[r * 16 + ch0]) > -126.0f;
        bool a1 = __fmul_rn(kl2, s_cm[r * 16 + ch1]) > -126.0f;
        float4 d40, d41;
        if (a0) d40 = *(const float4*)(drow + c4);          // loads first (MLP)
        if (a1) d41 = *(const float4*)(drow + c4 + 1024);
        if (a0) {
            acc0.x = fmaf(ex2a(__fmul_rn(kl2, d40.x)), rl, acc0.x);
            acc0.y = fmaf(ex2a(__fmul_rn(kl2, d40.y)), rl, acc0.y);
            acc0.z = fmaf(ex2a(__fmul_rn(kl2, d40.z)), rl, acc0.z);
            acc0.w = fmaf(ex2a(__fmul_rn(kl2, d40.w)), rl, acc0.w);
        }
        if (a1) {
            acc1.x = fmaf(ex2a(__fmul_rn(kl2, d41.x)), rl, acc1.x);
            acc1.y = fmaf(ex2a(__fmul_rn(kl2, d41.y)), rl, acc1.y);
            acc1.z = fmaf(ex2a(__fmul_rn(kl2, d41.z)), rl, acc1.z);
            acc1.w = fmaf(ex2a(__fmul_rn(kl2, d41.w)), rl, acc1.w);
        }
    }
    float* colA = g_colA + b * MM;
    if (acc0.x != 0.0f) atomicAdd(&colA[c4 + 0], acc0.x);
    if (acc0.y != 0.0f) atomicAdd(&colA[c4 + 1], acc0.y);
    if (acc0.z != 0.0f) atomicAdd(&colA[c4 + 2], acc0.z);
    if (acc0.w != 0.0f) atomicAdd(&colA[c4 + 3], acc0.w);
    if (acc1.x != 0.0f) atomicAdd(&colA[c4 + 1024], acc1.x);
    if (acc1.y != 0.0f) atomicAdd(&colA[c4 + 1025], acc1.y);
    if (acc1.z != 0.0f) atomicAdd(&colA[c4 + 1026], acc1.z);
    if (acc1.w != 0.0f) atomicAdd(&colA[c4 + 1027], acc1.w);
}

// --------------------------------------------------------------- kB
// ratioR inline; w = (w0*ratioL)*ratioR; register colsums (float4);
// rowsum via warp shuffle + per-warp smem atomic; cost in registers.
__global__ void kB(float kl2) {
    __shared__ alignas(16) float s_rr[MM];    // ratioR
    __shared__ float s_rl[8];
    __shared__ float s_rowsum[8];
    __shared__ float s_cost[8];
    __shared__ float s_cm[8 * 16];
    int b = blockIdx.y;
    int row0 = blockIdx.x * 8;
    for (int i = threadIdx.x; i < MM; i += 256)
        s_rr[i] = g_remainR[b * MM + i] / (g_colA[b * MM + i] + 1e-9f);
    if (threadIdx.x < 128)
        s_cm[threadIdx.x] = g_cmin[(size_t)(b * NN + row0) * 16 + threadIdx.x];
    if (threadIdx.x < 8) {
        s_rl[threadIdx.x] = g_ratioL[b * NN + row0 + threadIdx.x];
        s_rowsum[threadIdx.x] = 0.0f;
    }
    __syncthreads();
    int warp = threadIdx.x >> 5, lane = threadIdx.x & 31;
    int c4 = threadIdx.x * 4;
    int ch0 = warp, ch1 = warp + 8;
    float4 rr0 = *(const float4*)(s_rr + c4);
    float4 rr1 = *(const float4*)(s_rr + c4 + 1024);
    float4 col0 = make_float4(0, 0, 0, 0), col1 = make_float4(0, 0, 0, 0);
    float costw = 0.0f;
#pragma unroll 2
    for (int r = 0; r < 8; ++r) {
        float rl = s_rl[r];
        const float* drow = g_d2 + ((size_t)(b * NN + row0 + r)) * MM;
        bool a0 = (rl != 0.0f) && (__fmul_rn(kl2, s_cm[r * 16 + ch0]) > -126.0f);
        bool a1 = (rl != 0.0f) && (__fmul_rn(kl2, s_cm[r * 16 + ch1]) > -126.0f);
        float4 d40, d41;
        if (a0) d40 = *(const float4*)(drow + c4);
        if (a1) d41 = *(const float4*)(drow + c4 + 1024);
        float rowpart = 0.0f;
        if (a0) {
            float w0 = __fmul_rn(__fmul_rn(ex2a(__fmul_rn(kl2, d40.x)), rl), rr0.x);
            float w1 = __fmul_rn(__fmul_rn(ex2a(__fmul_rn(kl2, d40.y)), rl), rr0.y);
            float w2 = __fmul_rn(__fmul_rn(ex2a(__fmul_rn(kl2, d40.z)), rl), rr0.z);
            float w3 = __fmul_rn(__fmul_rn(ex2a(__fmul_rn(kl2, d40.w)), rl), rr0.w);
            col0.x = __fadd_rn(col0.x, w0); col0.y = __fadd_rn(col0.y, w1);
            col0.z = __fadd_rn(col0.z, w2); col0.w = __fadd_rn(col0.w, w3);
            rowpart = __fadd_rn(rowpart, __fadd_rn(__fadd_rn(w0, w1), __fadd_rn(w2, w3)));
            costw = fmaf(w0, sqrta(fmaxf(d40.x, 1e-24f)), costw);
            costw = fmaf(w1, sqrta(fmaxf(d40.y, 1e-24f)), costw);
            costw = fmaf(w2, sqrta(fmaxf(d40.z, 1e-24f)), costw);
            costw = fmaf(w3, sqrta(fmaxf(d40.w, 1e-24f)), costw);
        }
        if (a1) {
            float w0 = __fmul_rn(__fmul_rn(ex2a(__fmul_rn(kl2, d41.x)), rl), rr1.x);
            float w1 = __fmul_rn(__fmul_rn(ex2a(__fmul_rn(kl2, d41.y)), rl), rr1.y);
            float w2 = __fmul_rn(__fmul_rn(ex2a(__fmul_rn(kl2, d41.z)), rl), rr1.z);
            float w3 = __fmul_rn(__fmul_rn(ex2a(__fmul_rn(kl2, d41.w)), rl), rr1.w);
            col1.x = __fadd_rn(col1.x, w0); col1.y = __fadd_rn(col1.y, w1);
            col1.z = __fadd_rn(col1.z, w2); col1.w = __fadd_rn(col1.w, w3);
            rowpart = __fadd_rn(rowpart, __fadd_rn(__fadd_rn(w0, w1), __fadd_rn(w2, w3)));
            costw = fmaf(w0, sqrta(fmaxf(d41.x, 1e-24f)), costw);
            costw = fmaf(w1, sqrta(fmaxf(d41.y, 1e-24f)), costw);
            costw = fmaf(w2, sqrta(fmaxf(d41.z, 1e-24f)), costw);
            costw = fmaf(w3, sqrta(fmaxf(d41.w, 1e-24f)), costw);
        }
        if (__any_sync(0xffffffffu, rowpart != 0.0f)) {
#pragma unroll
            for (int o = 16; o; o >>= 1) rowpart += __shfl_xor_sync(0xffffffffu, rowpart, o);
            if (lane == 0) atomicAdd(&s_rowsum[r], rowpart);
        }
    }
    // cost reduction
#pragma unroll
    for (int o = 16; o; o >>= 1) costw += __shfl_xor_sync(0xffffffffu, costw, o);
    if (lane == 0) s_cost[warp] = costw;
    __syncthreads();
    if (threadIdx.x < 8) {
        size_t row = (size_t)(b * NN + row0 + threadIdx.x);
        g_remainL[row] = fmaxf(__fadd_rn(g_remainL[row], -s_rowsum[threadIdx.x]), 0.0f);
    }
    if (threadIdx.x == 0) {
        float cc = 0.0f;
#pragma unroll
        for (int w = 0; w < 8; ++w) cc += s_cost[w];
        if (cc != 0.0f) atomicAdd(&g_cost[b], cc);
    }
    float* colB = g_colB + b * MM;
    if (col0.x != 0.0f) atomicAdd(&colB[c4 + 0], col0.x);
    if (col0.y != 0.0f) atomicAdd(&colB[c4 + 1], col0.y);
    if (col0.z != 0.0f) atomicAdd(&colB[c4 + 2], col0.z);
    if (col0.w != 0.0f) atomicAdd(&colB[c4 + 3], col0.w);
    if (col1.x != 0.0f) atomicAdd(&colB[c4 + 1024], col1.x);
    if (col1.y != 0.0f) atomicAdd(&colB[c4 + 1025], col1.y);
    if (col1.z != 0.0f) atomicAdd(&colB[c4 + 1026], col1.z);
    if (col1.w != 0.0f) atomicAdd(&colB[c4 + 1027], col1.w);
}

// ---------------- remainR = max(remainR - colB, 0); reset col buffers
__global__ void kR() {
    int i = blockIdx.x * blockDim.x + threadIdx.x;
    if (i >= BB * MM) return;
    g_remainR[i] = fmaxf(__fadd_rn(g_remainR[i], -g_colB[i]), 0.0f);
    g_colA[i] = 0.0f;
    g_colB[i] = 0.0f;
}

__global__ void k_out(float* out) {
    out[0] = (g_cost[0] + g_cost[1] + g_cost[2] + g_cost[3]) * (1.0f / (BB * NN));
}

// ---------------------------------------------------------------- host
extern "C" void kernel_launch(void* const* d_in, const int* in_sizes, int n_in,
                              void* d_out, int out_size) {
    const float* tm = (const float*)d_in[0];
    const float* sr = (const float*)d_in[1];

    // levels: -4^7 .. -4^-1, then 0; pre-scaled by log2(e)
    const double L2E = 1.4426950408889634;
    float kl2[10];
    double lv = -16384.0;
    for (int j = 0; j < 8; ++j) { kl2[j] = (float)(lv * L2E); lv *= 0.25; }
    kl2[8] = (float)(-0.25 * L2E);
    kl2[9] = 0.0f;

    dim3 gM(256, BB);    // 8 rows per block -> 1024 blocks
    k_init<<<16, 512>>>();
    k_d2<<<dim3(256, BB), 256>>>(tm, sr);
    for (int j = 0; j < 10; ++j) {
        kA<<<gM, 256>>>(kl2[j]);
        kB<<<gM, 256>>>(kl2[j]);
        kR<<<16, 512>>>();
    }
    k_out<<<1, 1>>>((float*)d_out);
}

// round 9
// speedup vs baseline: 3.8432x; 1.2097x over previous
#include <cuda_runtime.h>
#include <math.h>

#define BB 4
#define NN 2048
#define MM 2048

// ---- persistent scratch (device globals; no allocation allowed) ----
__device__ __align__(16) float g_d2[BB * NN * MM];   // 64 MB squared distances (L2-resident)
__device__ float g_cmin[BB * NN * 16];               // per-row 128-col chunk minima
__device__ float g_remainL[BB * NN];
__device__ float g_remainR[BB * MM];
__device__ float g_ratioL[BB * NN];
__device__ float g_ratioR[BB * MM];
__device__ float g_colA[BB * MM];   // colsum of w0*ratioL (for ratioR)
__device__ float g_colB[BB * MM];   // colsum of w (for remainR update)
__device__ float g_cost[BB];

__device__ __forceinline__ float ex2a(float x) {
    float y; asm("ex2.approx.f32 %0, %1;" : "=f"(y) : "f"(x)); return y;
}
__device__ __forceinline__ float sqrta(float x) {
    float y; asm("sqrt.approx.f32 %0, %1;" : "=f"(y) : "f"(x)); return y;
}

// ------------- d2 (literal fp32 rounding) + chunk minima + state init
__global__ void k_d2(const float* __restrict__ tm, const float* __restrict__ sr) {
    __shared__ alignas(16) float sx[MM];
    __shared__ alignas(16) float sy[MM];
    __shared__ alignas(16) float sz[MM];
    int b = blockIdx.y;
    const float* sb = sr + (size_t)b * MM * 3;
    for (int i = threadIdx.x; i < MM; i += blockDim.x) {
        sx[i] = sb[3 * i]; sy[i] = sb[3 * i + 1]; sz[i] = sb[3 * i + 2];
    }
    if (blockIdx.x == 0) {       // fold k_init: one block per batch initializes state
        int bo = b * MM;
        for (int i = threadIdx.x; i < MM; i += blockDim.x) {
            g_remainL[b * NN + i] = 1.0f;   // multiL = 1 (N == M)
            g_remainR[bo + i] = 1.0f;
            g_colA[bo + i] = 0.0f;
            g_colB[bo + i] = 0.0f;
        }
        if (threadIdx.x == 0) g_cost[b] = 0.0f;
    }
    __syncthreads();
    int warp = threadIdx.x >> 5, lane = threadIdx.x & 31;
    int n = blockIdx.x * 8 + warp;
    size_t row = (size_t)(b * NN + n);
    const float* tp = tm + row * 3;
    float tx = tp[0], ty = tp[1], tz = tp[2];
    float* drow = g_d2 + row * MM;
#pragma unroll 2
    for (int it = 0; it < 16; ++it) {
        int m = it * 128 + lane * 4;
        float4 X = *(const float4*)(sx + m);
        float4 Y = *(const float4*)(sy + m);
        float4 Z = *(const float4*)(sz + m);
        float4 o;
        { float dx = __fadd_rn(tx, -X.x), dy = __fadd_rn(ty, -Y.x), dz = __fadd_rn(tz, -Z.x);
          o.x = __fadd_rn(__fadd_rn(__fmul_rn(dx, dx), __fmul_rn(dy, dy)), __fmul_rn(dz, dz)); }
        { float dx = __fadd_rn(tx, -X.y), dy = __fadd_rn(ty, -Y.y), dz = __fadd_rn(tz, -Z.y);
          o.y = __fadd_rn(__fadd_rn(__fmul_rn(dx, dx), __fmul_rn(dy, dy)), __fmul_rn(dz, dz)); }
        { float dx = __fadd_rn(tx, -X.z), dy = __fadd_rn(ty, -Y.z), dz = __fadd_rn(tz, -Z.z);
          o.z = __fadd_rn(__fadd_rn(__fmul_rn(dx, dx), __fmul_rn(dy, dy)), __fmul_rn(dz, dz)); }
        { float dx = __fadd_rn(tx, -X.w), dy = __fadd_rn(ty, -Y.w), dz = __fadd_rn(tz, -Z.w);
          o.w = __fadd_rn(__fadd_rn(__fmul_rn(dx, dx), __fmul_rn(dy, dy)), __fmul_rn(dz, dz)); }
        *(float4*)(drow + m) = o;
        float mn = fminf(fminf(o.x, o.y), fminf(o.z, o.w));
#pragma unroll
        for (int s = 16; s; s >>= 1) mn = fminf(mn, __shfl_xor_sync(0xffffffffu, mn, s));
        if (lane == 0) g_cmin[row * 16 + it] = mn;
    }
}

// --------------------------------------------------------------- kA
// 8 rows/block (grid 1024). Phase 1: suml -> ratioL (1 row/warp), remainR
// read straight from global (L2-hot). Phase 2 (column-ownership, float4):
// colA[c] += sum_rows w0*ratioL.
// Chunk skip: rn(kl2*cmin) <= -126 (log2 units) => all 128 ex2 flush to 0.
__global__ void __launch_bounds__(256, 5) kA(float kl2) {   // kl2 = level*log2(e)
    __shared__ float s_rl[8];
    __shared__ float s_cm[8 * 16];            // cmin cache for the block's rows
    int b = blockIdx.y;
    int row0 = blockIdx.x * 8;
    if (threadIdx.x < 128)
        s_cm[threadIdx.x] = g_cmin[(size_t)(b * NN + row0) * 16 + threadIdx.x];
    __syncthreads();
    int warp = threadIdx.x >> 5, lane = threadIdx.x & 31;
    // ---- phase 1: one row per warp
    {
        size_t row = (size_t)(b * NN + row0 + warp);
        const float* drow = g_d2 + row * MM;
        const float* rmg = g_remainR + b * MM;
        float suml = 0.0f;
#pragma unroll 2
        for (int it = 0; it < 16; ++it) {
            if (__fmul_rn(kl2, s_cm[warp * 16 + it]) > -126.0f) {
                int m = it * 128 + lane * 4;
                float4 d4 = *(const float4*)(drow + m);
                float4 rm = __ldg((const float4*)(rmg + m));
                suml = fmaf(ex2a(__fmul_rn(kl2, d4.x)), rm.x, suml);
                suml = fmaf(ex2a(__fmul_rn(kl2, d4.y)), rm.y, suml);
                suml = fmaf(ex2a(__fmul_rn(kl2, d4.z)), rm.z, suml);
                suml = fmaf(ex2a(__fmul_rn(kl2, d4.w)), rm.w, suml);
            }
        }
#pragma unroll
        for (int o = 16; o; o >>= 1) suml += __shfl_xor_sync(0xffffffffu, suml, o);
        if (lane == 0) {
            float rl = g_remainL[row] / (suml + 1e-9f);
            s_rl[warp] = rl;
            g_ratioL[row] = rl;
        }
    }
    __syncthreads();
    // ---- phase 2: thread owns cols 4*tid + 1024*k (k = 0,1)
    int c4 = threadIdx.x * 4;
    float4 acc0 = make_float4(0, 0, 0, 0), acc1 = make_float4(0, 0, 0, 0);
    int ch0 = warp, ch1 = warp + 8;   // warp-uniform chunk indices
#pragma unroll 2
    for (int r = 0; r < 8; ++r) {
        const float* drow = g_d2 + ((size_t)(b * NN + row0 + r)) * MM;
        float rl = s_rl[r];
        bool a0 = __fmul_rn(kl2, s_cm[r * 16 + ch0]) > -126.0f;
        bool a1 = __fmul_rn(kl2, s_cm[r * 16 + ch1]) > -126.0f;
        float4 d40, d41;
        if (a0) d40 = *(const float4*)(drow + c4);          // loads first (MLP)
        if (a1) d41 = *(const float4*)(drow + c4 + 1024);
        if (a0) {
            acc0.x = fmaf(ex2a(__fmul_rn(kl2, d40.x)), rl, acc0.x);
            acc0.y = fmaf(ex2a(__fmul_rn(kl2, d40.y)), rl, acc0.y);
            acc0.z = fmaf(ex2a(__fmul_rn(kl2, d40.z)), rl, acc0.z);
            acc0.w = fmaf(ex2a(__fmul_rn(kl2, d40.w)), rl, acc0.w);
        }
        if (a1) {
            acc1.x = fmaf(ex2a(__fmul_rn(kl2, d41.x)), rl, acc1.x);
            acc1.y = fmaf(ex2a(__fmul_rn(kl2, d41.y)), rl, acc1.y);
            acc1.z = fmaf(ex2a(__fmul_rn(kl2, d41.z)), rl, acc1.z);
            acc1.w = fmaf(ex2a(__fmul_rn(kl2, d41.w)), rl, acc1.w);
        }
    }
    float* colA = g_colA + b * MM;
    if (acc0.x != 0.0f) atomicAdd(&colA[c4 + 0], acc0.x);
    if (acc0.y != 0.0f) atomicAdd(&colA[c4 + 1], acc0.y);
    if (acc0.z != 0.0f) atomicAdd(&colA[c4 + 2], acc0.z);
    if (acc0.w != 0.0f) atomicAdd(&colA[c4 + 3], acc0.w);
    if (acc1.x != 0.0f) atomicAdd(&colA[c4 + 1024], acc1.x);
    if (acc1.y != 0.0f) atomicAdd(&colA[c4 + 1025], acc1.y);
    if (acc1.z != 0.0f) atomicAdd(&colA[c4 + 1026], acc1.z);
    if (acc1.w != 0.0f) atomicAdd(&colA[c4 + 1027], acc1.w);
}

// --------------- kC: ratioR = remainR/(colA+1e-9), computed ONCE
__global__ void kC() {
    int i = blockIdx.x * blockDim.x + threadIdx.x;
    if (i >= BB * MM) return;
    g_ratioR[i] = g_remainR[i] / (g_colA[i] + 1e-9f);
}

// --------------------------------------------------------------- kB
// ratioR from kC (two float4 ldg); w = (w0*ratioL)*ratioR; register colsums;
// rowsum via warp shuffle + per-warp smem atomic; cost in registers.
__global__ void __launch_bounds__(256, 5) kB(float kl2) {
    __shared__ float s_rl[8];
    __shared__ float s_rowsum[8];
    __shared__ float s_cost[8];
    __shared__ float s_cm[8 * 16];
    int b = blockIdx.y;
    int row0 = blockIdx.x * 8;
    if (threadIdx.x < 128)
        s_cm[threadIdx.x] = g_cmin[(size_t)(b * NN + row0) * 16 + threadIdx.x];
    if (threadIdx.x < 8) {
        s_rl[threadIdx.x] = g_ratioL[b * NN + row0 + threadIdx.x];
        s_rowsum[threadIdx.x] = 0.0f;
    }
    __syncthreads();
    int warp = threadIdx.x >> 5, lane = threadIdx.x & 31;
    int c4 = threadIdx.x * 4;
    int ch0 = warp, ch1 = warp + 8;
    float4 rr0 = __ldg((const float4*)(g_ratioR + b * MM + c4));
    float4 rr1 = __ldg((const float4*)(g_ratioR + b * MM + c4 + 1024));
    float4 col0 = make_float4(0, 0, 0, 0), col1 = make_float4(0, 0, 0, 0);
    float costw = 0.0f;
#pragma unroll 2
    for (int r = 0; r < 8; ++r) {
        float rl = s_rl[r];
        const float* drow = g_d2 + ((size_t)(b * NN + row0 + r)) * MM;
        bool a0 = (rl != 0.0f) && (__fmul_rn(kl2, s_cm[r * 16 + ch0]) > -126.0f);
        bool a1 = (rl != 0.0f) && (__fmul_rn(kl2, s_cm[r * 16 + ch1]) > -126.0f);
        float4 d40, d41;
        if (a0) d40 = *(const float4*)(drow + c4);
        if (a1) d41 = *(const float4*)(drow + c4 + 1024);
        float rowpart = 0.0f;
        if (a0) {
            float w0 = __fmul_rn(__fmul_rn(ex2a(__fmul_rn(kl2, d40.x)), rl), rr0.x);
            float w1 = __fmul_rn(__fmul_rn(ex2a(__fmul_rn(kl2, d40.y)), rl), rr0.y);
            float w2 = __fmul_rn(__fmul_rn(ex2a(__fmul_rn(kl2, d40.z)), rl), rr0.z);
            float w3 = __fmul_rn(__fmul_rn(ex2a(__fmul_rn(kl2, d40.w)), rl), rr0.w);
            col0.x = __fadd_rn(col0.x, w0); col0.y = __fadd_rn(col0.y, w1);
            col0.z = __fadd_rn(col0.z, w2); col0.w = __fadd_rn(col0.w, w3);
            rowpart = __fadd_rn(rowpart, __fadd_rn(__fadd_rn(w0, w1), __fadd_rn(w2, w3)));
            costw = fmaf(w0, sqrta(fmaxf(d40.x, 1e-24f)), costw);
            costw = fmaf(w1, sqrta(fmaxf(d40.y, 1e-24f)), costw);
            costw = fmaf(w2, sqrta(fmaxf(d40.z, 1e-24f)), costw);
            costw = fmaf(w3, sqrta(fmaxf(d40.w, 1e-24f)), costw);
        }
        if (a1) {
            float w0 = __fmul_rn(__fmul_rn(ex2a(__fmul_rn(kl2, d41.x)), rl), rr1.x);
            float w1 = __fmul_rn(__fmul_rn(ex2a(__fmul_rn(kl2, d41.y)), rl), rr1.y);
            float w2 = __fmul_rn(__fmul_rn(ex2a(__fmul_rn(kl2, d41.z)), rl), rr1.z);
            float w3 = __fmul_rn(__fmul_rn(ex2a(__fmul_rn(kl2, d41.w)), rl), rr1.w);
            col1.x = __fadd_rn(col1.x, w0); col1.y = __fadd_rn(col1.y, w1);
            col1.z = __fadd_rn(col1.z, w2); col1.w = __fadd_rn(col1.w, w3);
            rowpart = __fadd_rn(rowpart, __fadd_rn(__fadd_rn(w0, w1), __fadd_rn(w2, w3)));
            costw = fmaf(w0, sqrta(fmaxf(d41.x, 1e-24f)), costw);
            costw = fmaf(w1, sqrta(fmaxf(d41.y, 1e-24f)), costw);
            costw = fmaf(w2, sqrta(fmaxf(d41.z, 1e-24f)), costw);
            costw = fmaf(w3, sqrta(fmaxf(d41.w, 1e-24f)), costw);
        }
        if (__any_sync(0xffffffffu, rowpart != 0.0f)) {
#pragma unroll
            for (int o = 16; o; o >>= 1) rowpart += __shfl_xor_sync(0xffffffffu, rowpart, o);
            if (lane == 0) atomicAdd(&s_rowsum[r], rowpart);
        }
    }
    // cost reduction
#pragma unroll
    for (int o = 16; o; o >>= 1) costw += __shfl_xor_sync(0xffffffffu, costw, o);
    if (lane == 0) s_cost[warp] = costw;
    __syncthreads();
    if (threadIdx.x < 8) {
        size_t row = (size_t)(b * NN + row0 + threadIdx.x);
        g_remainL[row] = fmaxf(__fadd_rn(g_remainL[row], -s_rowsum[threadIdx.x]), 0.0f);
    }
    if (threadIdx.x == 0) {
        float cc = 0.0f;
#pragma unroll
        for (int w = 0; w < 8; ++w) cc += s_cost[w];
        if (cc != 0.0f) atomicAdd(&g_cost[b], cc);
    }
    float* colB = g_colB + b * MM;
    if (col0.x != 0.0f) atomicAdd(&colB[c4 + 0], col0.x);
    if (col0.y != 0.0f) atomicAdd(&colB[c4 + 1], col0.y);
    if (col0.z != 0.0f) atomicAdd(&colB[c4 + 2], col0.z);
    if (col0.w != 0.0f) atomicAdd(&colB[c4 + 3], col0.w);
    if (col1.x != 0.0f) atomicAdd(&colB[c4 + 1024], col1.x);
    if (col1.y != 0.0f) atomicAdd(&colB[c4 + 1025], col1.y);
    if (col1.z != 0.0f) atomicAdd(&colB[c4 + 1026], col1.z);
    if (col1.w != 0.0f) atomicAdd(&colB[c4 + 1027], col1.w);
}

// ---------------- remainR = max(remainR - colB, 0); reset col buffers
__global__ void kR() {
    int i = blockIdx.x * blockDim.x + threadIdx.x;
    if (i >= BB * MM) return;
    g_remainR[i] = fmaxf(__fadd_rn(g_remainR[i], -g_colB[i]), 0.0f);
    g_colA[i] = 0.0f;
    g_colB[i] = 0.0f;
}

__global__ void k_out(float* out) {
    out[0] = (g_cost[0] + g_cost[1] + g_cost[2] + g_cost[3]) * (1.0f / (BB * NN));
}

// ---------------------------------------------------------------- host
extern "C" void kernel_launch(void* const* d_in, const int* in_sizes, int n_in,
                              void* d_out, int out_size) {
    const float* tm = (const float*)d_in[0];
    const float* sr = (const float*)d_in[1];

    // levels: -4^7 .. -4^-1, then 0; pre-scaled by log2(e)
    const double L2E = 1.4426950408889634;
    float kl2[10];
    double lv = -16384.0;
    for (int j = 0; j < 8; ++j) { kl2[j] = (float)(lv * L2E); lv *= 0.25; }
    kl2[8] = (float)(-0.25 * L2E);
    kl2[9] = 0.0f;

    dim3 gM(256, BB);    // 8 rows per block -> 1024 blocks
    k_d2<<<dim3(256, BB), 256>>>(tm, sr);
    for (int j = 0; j < 10; ++j) {
        kA<<<gM, 256>>>(kl2[j]);
        kC<<<16, 512>>>();
        kB<<<gM, 256>>>(kl2[j]);
        kR<<<16, 512>>>();
    }
    k_out<<<1, 1>>>((float*)d_out);
}